// round 13
// baseline (speedup 1.0000x reference)
#include <cuda_runtime.h>
#include <cuda_fp16.h>
#include <math.h>

// Radon transform: x (4,1,384,384) f32 -> out (4, 460, 64) f32
// pad=38, Hp=Wp=460, 64 angles at a*2.8125 deg.
//
// R13 = R12 (pair-packed fp16 scratch, 90-deg symmetry, dual layouts)
//  + prep split per layout: 1250 blocks -> full occupancy (was 49%, grid-capped)
//  + radon: unroll 7, __float2int_rd-based coord decompose.

#define IH 384
#define IW 384
#define PAD 38
#define HP 460
#define WP 460
#define NA 64
#define NB 4

#define QR 385            // valid floor-coord index range [0,384]
#define PR 386            // stored point rows 0..385
#define PC 392            // point row stride: 392*16B = 49 x 128B lines
#define QBASE (PAD - 1)
#define NWB   115         // 4-i groups per angle
#define NWBG  29          // groups of 4 i-groups (16 i's per block)
#define NT2   25          // 16-point tiles per axis (400 >= 386)

// 2 layouts * 386 * 392 * 16B = 4.84 MB (.bss).
// g_p[l][r][c] = { h2(b: px[r-1][c-1], px[r-1][c]) for b=0..3 }  (l=0)
__device__ uint4 g_p[2][PR][PC];
// Column partials: [group][(b*32+a)*460 + j], 6.8 MB, fully rewritten.
__device__ float g_colpart[NWBG][NB * 32 * HP];

__device__ __forceinline__ unsigned packh2(float a, float b) {
    __half2 h = __floats2half2_rn(a, b);
    return *reinterpret_cast<unsigned*>(&h);
}

// One block per (layout, 16x16 point tile). Loads the 17x17 image tile of all
// 4 batches, emits its layout's points. 1250 blocks -> full occupancy.
__global__ __launch_bounds__(256) void prep_kernel(const float* __restrict__ x) {
    __shared__ float sh[NB][17][17];

    int bid = blockIdx.x;
    int tc = bid % NT2; bid /= NT2;
    int tr = bid % NT2;
    int l  = bid / NT2;

    int R0 = tr * 16 - 1;    // image row of sh[][0][.]
    int C0 = tc * 16 - 1;    // image col of sh[][.][0]

    for (int idx = threadIdx.x; idx < NB * 17 * 17; idx += 256) {
        int k  = idx / (17 * 17);
        int rc = idx - k * (17 * 17);
        int yy = rc / 17, xx = rc - yy * 17;
        int gy = R0 + yy, gx = C0 + xx;
        float v = 0.0f;
        if (((unsigned)gy < IH) & ((unsigned)gx < IW))
            v = __ldg(x + k * (IH * IW) + gy * IW + gx);
        sh[k][yy][xx] = v;
    }
    __syncthreads();

    int rl = threadIdx.x >> 4, cl = threadIdx.x & 15;

    if (l == 0) {
        // point(rp,cp) = h2( img[rp-1][cp-1], img[rp-1][cp] )
        int rp = tr * 16 + rl, cp = tc * 16 + cl;
        if ((rp < PR) & (cp < QR)) {
            uint4 v;
            v.x = packh2(sh[0][rl][cl], sh[0][rl][cl + 1]);
            v.y = packh2(sh[1][rl][cl], sh[1][rl][cl + 1]);
            v.z = packh2(sh[2][rl][cl], sh[2][rl][cl + 1]);
            v.w = packh2(sh[3][rl][cl], sh[3][rl][cl + 1]);
            g_p[0][rp][cp] = v;
        }
    } else {
        // point(RP,CP) = h2( img[CP-1][RP-1], img[CP][RP-1] ),
        // RP = tc*16+rl, CP = tr*16+cl  (reads sh[cl][rl], sh[cl+1][rl])
        int RP = tc * 16 + rl, CP = tr * 16 + cl;
        if ((RP < PR) & (CP < QR)) {
            uint4 v;
            v.x = packh2(sh[0][cl][rl], sh[0][cl + 1][rl]);
            v.y = packh2(sh[1][cl][rl], sh[1][cl + 1][rl]);
            v.z = packh2(sh[2][cl][rl], sh[2][cl + 1][rl]);
            v.w = packh2(sh[3][cl][rl], sh[3][cl + 1][rl]);
            g_p[1][RP][CP] = v;
        }
    }
}

__device__ __forceinline__ float lerp2(unsigned top, unsigned bot,
                                       float wC, float wR) {
    float2 t = __half22float2(*reinterpret_cast<const __half2*>(&top));
    float2 b = __half22float2(*reinterpret_cast<const __half2*>(&bot));
    float h0 = fmaf(wC, t.y - t.x, t.x);
    float h1 = fmaf(wC, b.y - b.x, b.x);
    return fmaf(wR, h1 - h0, h0);
}

// Block = (a<32, wgrp): 8 warps = 4 i-groups (wl) x 2 j-halves.
// Warp: i = (wgrp*4 + wl)*4 + isub, lane = isub*8 + jsub; j over its half.
// Each warp produces ALL 4 batches.
__global__ __launch_bounds__(256) void radon_kernel(float* __restrict__ out)
{
    __shared__ float colsh[NB][4][464];
    __shared__ float rowsh[NB][16][2];

    const int wgrp = blockIdx.x % NWBG;
    const int a    = blockIdx.x / NWBG;

    const int wid   = threadIdx.x >> 5;
    const int lane  = threadIdx.x & 31;
    const int wl    = wid & 3;
    const int jhalf = wid >> 2;
    const int wblk  = wgrp * 4 + wl;
    const bool valid = (wblk < NWB);

    const int isub = lane >> 3;
    const int jsub = lane & 7;
    const int i    = wblk * 4 + isub;
    const int il   = wl * 4 + isub;          // i_local in [0,16)

    float c, s;
    {
        float deg = 2.8125f * (float)a;
        float th  = deg * (float)(3.14159265358979323846 / 180.0);
        sincosf(th, &s, &c);
    }

    if (valid) {
        const float u  = (float)i - 229.5f;
        const float SH = 229.5f - (float)QBASE;

        const bool tmode = fabsf(c) > fabsf(s);
        const float Rv = tmode ? -s : c;
        const float Cv = tmode ?  c : -s;
        const float R0 = (tmode ? c * u : s * u) + SH;
        const float C0 = (tmode ? s * u : c * u) + SH;
        const uint4* __restrict__ base = &g_p[tmode ? 1 : 0][0][0];

        float acc0 = 0.f, acc1 = 0.f, acc2 = 0.f, acc3 = 0.f;
        const int j0 = jhalf * 232;
        float vf = (float)(j0 + jsub) - 229.5f;
        int   j  = j0 + jsub;

        // jhalf0: 29 full iters (j<232). jhalf1: 28 full + tail (j<460).
        #pragma unroll 7
        for (int it = 0; it < 28; ++it, vf += 8.0f, j += 8) {
            float R = fmaf(Rv, vf, R0);
            float C = fmaf(Cv, vf, C0);
            int   rq = __float2int_rd(R);
            int   cq = __float2int_rd(C);
            float wR = R - (float)rq;
            float wC = C - (float)cq;

            float v0 = 0.f, v1 = 0.f, v2 = 0.f, v3 = 0.f;
            if (((unsigned)rq < (unsigned)QR) & ((unsigned)cq < (unsigned)QR)) {
                const uint4* p = base + rq * PC + cq;
                uint4 P0 = __ldg(p);
                uint4 P1 = __ldg(p + PC);
                v0 = lerp2(P0.x, P1.x, wC, wR);
                v1 = lerp2(P0.y, P1.y, wC, wR);
                v2 = lerp2(P0.z, P1.z, wC, wR);
                v3 = lerp2(P0.w, P1.w, wC, wR);
            }
            acc0 += v0; acc1 += v1; acc2 += v2; acc3 += v3;
            v0 += __shfl_xor_sync(0xffffffffu, v0, 8);
            v0 += __shfl_xor_sync(0xffffffffu, v0, 16);
            v1 += __shfl_xor_sync(0xffffffffu, v1, 8);
            v1 += __shfl_xor_sync(0xffffffffu, v1, 16);
            v2 += __shfl_xor_sync(0xffffffffu, v2, 8);
            v2 += __shfl_xor_sync(0xffffffffu, v2, 16);
            v3 += __shfl_xor_sync(0xffffffffu, v3, 8);
            v3 += __shfl_xor_sync(0xffffffffu, v3, 16);
            if (isub == 0) {
                colsh[0][wl][j] = v0; colsh[1][wl][j] = v1;
                colsh[2][wl][j] = v2; colsh[3][wl][j] = v3;
            }
        }
        {   // iteration 29: jhalf0 full (j=224..231); jhalf1 only jsub<4 (456..459)
            bool ok = (jhalf == 0) | (jsub < 4);
            float v0 = 0.f, v1 = 0.f, v2 = 0.f, v3 = 0.f;
            if (ok) {
                float R = fmaf(Rv, vf, R0);
                float C = fmaf(Cv, vf, C0);
                int   rq = __float2int_rd(R);
                int   cq = __float2int_rd(C);
                float wR = R - (float)rq;
                float wC = C - (float)cq;
                if (((unsigned)rq < (unsigned)QR) & ((unsigned)cq < (unsigned)QR)) {
                    const uint4* p = base + rq * PC + cq;
                    uint4 P0 = __ldg(p);
                    uint4 P1 = __ldg(p + PC);
                    v0 = lerp2(P0.x, P1.x, wC, wR);
                    v1 = lerp2(P0.y, P1.y, wC, wR);
                    v2 = lerp2(P0.z, P1.z, wC, wR);
                    v3 = lerp2(P0.w, P1.w, wC, wR);
                }
            }
            acc0 += v0; acc1 += v1; acc2 += v2; acc3 += v3;
            v0 += __shfl_xor_sync(0xffffffffu, v0, 8);
            v0 += __shfl_xor_sync(0xffffffffu, v0, 16);
            v1 += __shfl_xor_sync(0xffffffffu, v1, 8);
            v1 += __shfl_xor_sync(0xffffffffu, v1, 16);
            v2 += __shfl_xor_sync(0xffffffffu, v2, 8);
            v2 += __shfl_xor_sync(0xffffffffu, v2, 16);
            v3 += __shfl_xor_sync(0xffffffffu, v3, 8);
            v3 += __shfl_xor_sync(0xffffffffu, v3, 16);
            if ((isub == 0) & ok) {
                colsh[0][wl][j] = v0; colsh[1][wl][j] = v1;
                colsh[2][wl][j] = v2; colsh[3][wl][j] = v3;
            }
        }

        // row partial: reduce each acc over the 8 jsub lanes
        #pragma unroll
        for (int off = 4; off; off >>= 1) {
            acc0 += __shfl_xor_sync(0xffffffffu, acc0, off);
            acc1 += __shfl_xor_sync(0xffffffffu, acc1, off);
            acc2 += __shfl_xor_sync(0xffffffffu, acc2, off);
            acc3 += __shfl_xor_sync(0xffffffffu, acc3, off);
        }
        if (jsub == 0) {
            rowsh[0][il][jhalf] = acc0;
            rowsh[1][il][jhalf] = acc1;
            rowsh[2][il][jhalf] = acc2;
            rowsh[3][il][jhalf] = acc3;
        }
    } else {
        // invalid warp (only wgrp=28, wl=3): zero its colsh range + rowsh rows
        const int j0 = jhalf * 232, j1 = jhalf ? 460 : 232;
        for (int j = j0 + lane; j < j1; j += 32) {
            colsh[0][wl][j] = 0.f; colsh[1][wl][j] = 0.f;
            colsh[2][wl][j] = 0.f; colsh[3][wl][j] = 0.f;
        }
        if (jsub == 0) {
            rowsh[0][il][jhalf] = 0.f; rowsh[1][il][jhalf] = 0.f;
            rowsh[2][il][jhalf] = 0.f; rowsh[3][il][jhalf] = 0.f;
        }
    }

    __syncthreads();

    // row outputs: 4 batches x 16 i_locals -> angle a+32
    if (threadIdx.x < NB * 16) {
        int b  = threadIdx.x >> 4;
        int il2 = threadIdx.x & 15;
        int ii = wgrp * 16 + il2;
        if (ii < 460) {
            float v = rowsh[b][il2][0] + rowsh[b][il2][1];
            out[(b * HP + (459 - ii)) * NA + (a + 32)] = v * (1.0f / (float)WP);
        }
    }

    // column partials: reduce 4 wl slices per (b, j)
    for (int t = threadIdx.x; t < NB * HP; t += 256) {
        int b = t / HP, j = t - b * HP;
        float sum = colsh[b][0][j] + colsh[b][1][j]
                  + colsh[b][2][j] + colsh[b][3][j];
        g_colpart[wgrp][(b * 32 + a) * HP + j] = sum;
    }
}

// Sum the 29 group partials per (b, a<32, j) -> angle a output.
__global__ __launch_bounds__(256) void combine_kernel(float* __restrict__ out)
{
    int t = blockIdx.x * blockDim.x + threadIdx.x;
    if (t >= NB * 32 * HP) return;
    float sum = 0.0f;
    #pragma unroll
    for (int g = 0; g < NWBG; ++g)
        sum += g_colpart[g][t];
    int j  = t % HP;
    int ba = t / HP;
    int a  = ba & 31;
    int b  = ba >> 5;
    out[(b * HP + j) * NA + a] = sum * (1.0f / (float)WP);
}

extern "C" void kernel_launch(void* const* d_in, const int* in_sizes, int n_in,
                              void* d_out, int out_size) {
    (void)in_sizes; (void)n_in; (void)out_size;
    const float* x = (const float*)d_in[0];
    float* out = (float*)d_out;

    prep_kernel<<<2 * NT2 * NT2, 256>>>(x);        // 1250 blocks

    radon_kernel<<<32 * NWBG, 256>>>(out);         // 928 blocks

    const int ncomb = NB * 32 * HP;                 // 58880
    combine_kernel<<<(ncomb + 255) / 256, 256>>>(out);
}

// round 16
// speedup vs baseline: 1.0284x; 1.0284x over previous
#include <cuda_runtime.h>
#include <cuda_fp16.h>
#include <math.h>
#include <string.h>

// Radon transform: x (4,1,384,384) f32 -> out (4, 460, 64) f32
// pad=38, Hp=Wp=460, 64 angles at a*2.8125 deg.
//
// R16 = R14 semantics (pair-packed fp16 scratch in batch-major half2 order,
// fused prep, 90-deg symmetry, HFMA2 horizontal lerp, fp32 vertical lerp)
// with all bit-casts rewritten via memcpy (no pointer reinterpret_cast UB).

#define IH 384
#define IW 384
#define PAD 38
#define HP 460
#define WP 460
#define NA 64
#define NB 4

#define QR 385            // valid floor-coord index range [0,384]
#define PR 386            // stored point rows 0..385
#define PC 392            // point row stride: 392*16B = 49 x 128B lines
#define QBASE (PAD - 1)
#define NWB   115         // 4-i groups per angle
#define NWBG  29          // groups of 4 i-groups (16 i's per block)
#define NT2   25          // 16-point tiles per axis (400 >= 386)

// 2 layouts * 386 * 392 * 16B = 4.84 MB (.bss).
// g_p[l][r][c] = { h2(b0.L,b1.L), h2(b0.R,b1.R), h2(b2.L,b3.L), h2(b2.R,b3.R) }
// where L = px[r-1][c-1], R = px[r-1][c] (layout 0; transposed for l=1).
__device__ uint4 g_p[2][PR][PC];
// Column partials: [group][(b*32+a)*460 + j], 6.8 MB, fully rewritten.
__device__ float g_colpart[NWBG][NB * 32 * HP];

__device__ __forceinline__ unsigned packh2(float a, float b) {
    __half2 h = __floats2half2_rn(a, b);
    unsigned u;
    memcpy(&u, &h, 4);
    return u;
}

__device__ __forceinline__ __half2 h2cast(unsigned u) {
    __half2 h;
    memcpy(&h, &u, 4);
    return h;
}

// One block per 16x16 point tile (fused: both layouts from one tile load).
__global__ __launch_bounds__(256) void prep_kernel(const float* __restrict__ x) {
    __shared__ float sh[NB][17][17];

    int bid = blockIdx.x;
    int tc = bid % NT2;
    int tr = bid / NT2;

    int R0 = tr * 16 - 1;    // image row of sh[][0][.]
    int C0 = tc * 16 - 1;    // image col of sh[][.][0]

    for (int idx = threadIdx.x; idx < NB * 17 * 17; idx += 256) {
        int k  = idx / (17 * 17);
        int rc = idx - k * (17 * 17);
        int yy = rc / 17, xx = rc - yy * 17;
        int gy = R0 + yy, gx = C0 + xx;
        float v = 0.0f;
        if (((unsigned)gy < IH) & ((unsigned)gx < IW))
            v = __ldg(x + k * (IH * IW) + gy * IW + gx);
        sh[k][yy][xx] = v;
    }
    __syncthreads();

    int rl = threadIdx.x >> 4, cl = threadIdx.x & 15;

    // layout 0: L=sh[b][rl][cl], R=sh[b][rl][cl+1]
    {
        int rp = tr * 16 + rl, cp = tc * 16 + cl;
        if ((rp < PR) & (cp < QR)) {
            uint4 v;
            v.x = packh2(sh[0][rl][cl],     sh[1][rl][cl]);
            v.y = packh2(sh[0][rl][cl + 1], sh[1][rl][cl + 1]);
            v.z = packh2(sh[2][rl][cl],     sh[3][rl][cl]);
            v.w = packh2(sh[2][rl][cl + 1], sh[3][rl][cl + 1]);
            g_p[0][rp][cp] = v;
        }
    }
    // layout 1 (transposed): L=sh[b][cl][rl], R=sh[b][cl+1][rl],
    // RP = tc*16+rl, CP = tr*16+cl
    {
        int RP = tc * 16 + rl, CP = tr * 16 + cl;
        if ((RP < PR) & (CP < QR)) {
            uint4 v;
            v.x = packh2(sh[0][cl][rl],     sh[1][cl][rl]);
            v.y = packh2(sh[0][cl + 1][rl], sh[1][cl + 1][rl]);
            v.z = packh2(sh[2][cl][rl],     sh[3][cl][rl]);
            v.w = packh2(sh[2][cl + 1][rl], sh[3][cl + 1][rl]);
            g_p[1][RP][CP] = v;
        }
    }
}

// Horizontal lerp for 2 batches at once (fp16), returns {b_even, b_odd}.
__device__ __forceinline__ __half2 hlerp2(unsigned L, unsigned R, __half2 wC2) {
    __half2 l = h2cast(L), r = h2cast(R);
    return __hfma2(wC2, __hsub2(r, l), l);
}

// Block = (a<32, wgrp): 8 warps = 4 i-groups (wl) x 2 j-halves.
// Warp: i = (wgrp*4 + wl)*4 + isub, lane = isub*8 + jsub; j over its half.
// Each warp produces ALL 4 batches.
__global__ __launch_bounds__(256) void radon_kernel(float* __restrict__ out)
{
    __shared__ float colsh[NB][4][464];
    __shared__ float rowsh[NB][16][2];

    const int wgrp = blockIdx.x % NWBG;
    const int a    = blockIdx.x / NWBG;

    const int wid   = threadIdx.x >> 5;
    const int lane  = threadIdx.x & 31;
    const int wl    = wid & 3;
    const int jhalf = wid >> 2;
    const int wblk  = wgrp * 4 + wl;
    const bool valid = (wblk < NWB);

    const int isub = lane >> 3;
    const int jsub = lane & 7;
    const int i    = wblk * 4 + isub;
    const int il   = wl * 4 + isub;          // i_local in [0,16)

    float c, s;
    {
        float deg = 2.8125f * (float)a;
        float th  = deg * (float)(3.14159265358979323846 / 180.0);
        sincosf(th, &s, &c);
    }

    if (valid) {
        const float u  = (float)i - 229.5f;
        const float SH = 229.5f - (float)QBASE;

        const bool tmode = fabsf(c) > fabsf(s);
        const float Rv = tmode ? -s : c;
        const float Cv = tmode ?  c : -s;
        const float R0 = (tmode ? c * u : s * u) + SH;
        const float C0 = (tmode ? s * u : c * u) + SH;
        const uint4* __restrict__ base = &g_p[tmode ? 1 : 0][0][0];

        float acc0 = 0.f, acc1 = 0.f, acc2 = 0.f, acc3 = 0.f;
        const int j0 = jhalf * 232;
        float vf = (float)(j0 + jsub) - 229.5f;
        int   j  = j0 + jsub;

        // jhalf0: 29 full iters (j<232). jhalf1: 28 full + tail (j<460).
        #pragma unroll 4
        for (int it = 0; it < 28; ++it, vf += 8.0f, j += 8) {
            float R = fmaf(Rv, vf, R0);
            float C = fmaf(Cv, vf, C0);
            int   rq = __float2int_rd(R);
            int   cq = __float2int_rd(C);
            float wR = R - (float)rq;
            float wC = C - (float)cq;

            float v0 = 0.f, v1 = 0.f, v2 = 0.f, v3 = 0.f;
            if (((unsigned)rq < (unsigned)QR) & ((unsigned)cq < (unsigned)QR)) {
                const uint4* p = base + rq * PC + cq;
                uint4 P0 = __ldg(p);
                uint4 P1 = __ldg(p + PC);
                __half2 wC2 = __float2half2_rn(wC);
                float2 t01 = __half22float2(hlerp2(P0.x, P0.y, wC2));
                float2 b01 = __half22float2(hlerp2(P1.x, P1.y, wC2));
                float2 t23 = __half22float2(hlerp2(P0.z, P0.w, wC2));
                float2 b23 = __half22float2(hlerp2(P1.z, P1.w, wC2));
                v0 = fmaf(wR, b01.x - t01.x, t01.x);
                v1 = fmaf(wR, b01.y - t01.y, t01.y);
                v2 = fmaf(wR, b23.x - t23.x, t23.x);
                v3 = fmaf(wR, b23.y - t23.y, t23.y);
            }
            acc0 += v0; acc1 += v1; acc2 += v2; acc3 += v3;
            v0 += __shfl_xor_sync(0xffffffffu, v0, 8);
            v0 += __shfl_xor_sync(0xffffffffu, v0, 16);
            v1 += __shfl_xor_sync(0xffffffffu, v1, 8);
            v1 += __shfl_xor_sync(0xffffffffu, v1, 16);
            v2 += __shfl_xor_sync(0xffffffffu, v2, 8);
            v2 += __shfl_xor_sync(0xffffffffu, v2, 16);
            v3 += __shfl_xor_sync(0xffffffffu, v3, 8);
            v3 += __shfl_xor_sync(0xffffffffu, v3, 16);
            if (isub == 0) {
                colsh[0][wl][j] = v0; colsh[1][wl][j] = v1;
                colsh[2][wl][j] = v2; colsh[3][wl][j] = v3;
            }
        }
        {   // iteration 29: jhalf0 full (j=224..231); jhalf1 only jsub<4 (456..459)
            bool ok = (jhalf == 0) | (jsub < 4);
            float v0 = 0.f, v1 = 0.f, v2 = 0.f, v3 = 0.f;
            if (ok) {
                float R = fmaf(Rv, vf, R0);
                float C = fmaf(Cv, vf, C0);
                int   rq = __float2int_rd(R);
                int   cq = __float2int_rd(C);
                float wR = R - (float)rq;
                float wC = C - (float)cq;
                if (((unsigned)rq < (unsigned)QR) & ((unsigned)cq < (unsigned)QR)) {
                    const uint4* p = base + rq * PC + cq;
                    uint4 P0 = __ldg(p);
                    uint4 P1 = __ldg(p + PC);
                    __half2 wC2 = __float2half2_rn(wC);
                    float2 t01 = __half22float2(hlerp2(P0.x, P0.y, wC2));
                    float2 b01 = __half22float2(hlerp2(P1.x, P1.y, wC2));
                    float2 t23 = __half22float2(hlerp2(P0.z, P0.w, wC2));
                    float2 b23 = __half22float2(hlerp2(P1.z, P1.w, wC2));
                    v0 = fmaf(wR, b01.x - t01.x, t01.x);
                    v1 = fmaf(wR, b01.y - t01.y, t01.y);
                    v2 = fmaf(wR, b23.x - t23.x, t23.x);
                    v3 = fmaf(wR, b23.y - t23.y, t23.y);
                }
            }
            acc0 += v0; acc1 += v1; acc2 += v2; acc3 += v3;
            v0 += __shfl_xor_sync(0xffffffffu, v0, 8);
            v0 += __shfl_xor_sync(0xffffffffu, v0, 16);
            v1 += __shfl_xor_sync(0xffffffffu, v1, 8);
            v1 += __shfl_xor_sync(0xffffffffu, v1, 16);
            v2 += __shfl_xor_sync(0xffffffffu, v2, 8);
            v2 += __shfl_xor_sync(0xffffffffu, v2, 16);
            v3 += __shfl_xor_sync(0xffffffffu, v3, 8);
            v3 += __shfl_xor_sync(0xffffffffu, v3, 16);
            if ((isub == 0) & ok) {
                colsh[0][wl][j] = v0; colsh[1][wl][j] = v1;
                colsh[2][wl][j] = v2; colsh[3][wl][j] = v3;
            }
        }

        // row partial: reduce each acc over the 8 jsub lanes
        #pragma unroll
        for (int off = 4; off; off >>= 1) {
            acc0 += __shfl_xor_sync(0xffffffffu, acc0, off);
            acc1 += __shfl_xor_sync(0xffffffffu, acc1, off);
            acc2 += __shfl_xor_sync(0xffffffffu, acc2, off);
            acc3 += __shfl_xor_sync(0xffffffffu, acc3, off);
        }
        if (jsub == 0) {
            rowsh[0][il][jhalf] = acc0;
            rowsh[1][il][jhalf] = acc1;
            rowsh[2][il][jhalf] = acc2;
            rowsh[3][il][jhalf] = acc3;
        }
    } else {
        // invalid warp (only wgrp=28, wl=3): zero its colsh range + rowsh rows
        const int j0 = jhalf * 232, j1 = jhalf ? 460 : 232;
        for (int j = j0 + lane; j < j1; j += 32) {
            colsh[0][wl][j] = 0.f; colsh[1][wl][j] = 0.f;
            colsh[2][wl][j] = 0.f; colsh[3][wl][j] = 0.f;
        }
        if (jsub == 0) {
            rowsh[0][il][jhalf] = 0.f; rowsh[1][il][jhalf] = 0.f;
            rowsh[2][il][jhalf] = 0.f; rowsh[3][il][jhalf] = 0.f;
        }
    }

    __syncthreads();

    // row outputs: 4 batches x 16 i_locals -> angle a+32
    if (threadIdx.x < NB * 16) {
        int b  = threadIdx.x >> 4;
        int il2 = threadIdx.x & 15;
        int ii = wgrp * 16 + il2;
        if (ii < 460) {
            float v = rowsh[b][il2][0] + rowsh[b][il2][1];
            out[(b * HP + (459 - ii)) * NA + (a + 32)] = v * (1.0f / (float)WP);
        }
    }

    // column partials: reduce 4 wl slices per (b, j)
    for (int t = threadIdx.x; t < NB * HP; t += 256) {
        int b = t / HP, j = t - b * HP;
        float sum = colsh[b][0][j] + colsh[b][1][j]
                  + colsh[b][2][j] + colsh[b][3][j];
        g_colpart[wgrp][(b * 32 + a) * HP + j] = sum;
    }
}

// Sum the 29 group partials per (b, a<32, j) -> angle a output.
__global__ __launch_bounds__(256) void combine_kernel(float* __restrict__ out)
{
    int t = blockIdx.x * blockDim.x + threadIdx.x;
    if (t >= NB * 32 * HP) return;
    float sum = 0.0f;
    #pragma unroll
    for (int g = 0; g < NWBG; ++g)
        sum += g_colpart[g][t];
    int j  = t % HP;
    int ba = t / HP;
    int a  = ba & 31;
    int b  = ba >> 5;
    out[(b * HP + j) * NA + a] = sum * (1.0f / (float)WP);
}

extern "C" void kernel_launch(void* const* d_in, const int* in_sizes, int n_in,
                              void* d_out, int out_size) {
    (void)in_sizes; (void)n_in; (void)out_size;
    const float* x = (const float*)d_in[0];
    float* out = (float*)d_out;

    prep_kernel<<<NT2 * NT2, 256>>>(x);            // 625 blocks

    radon_kernel<<<32 * NWBG, 256>>>(out);         // 928 blocks

    const int ncomb = NB * 32 * HP;                 // 58880
    combine_kernel<<<(ncomb + 255) / 256, 256>>>(out);
}

// round 17
// speedup vs baseline: 1.0491x; 1.0201x over previous
#include <cuda_runtime.h>
#include <cuda_fp16.h>
#include <math.h>
#include <string.h>

// Radon transform: x (4,1,384,384) f32 -> out (4, 460, 64) f32
// pad=38, Hp=Wp=460, 64 angles at a*2.8125 deg.
//
// R17 = R12 radon (pair-packed fp16 scratch, scalar fp32 lerp -- best
// measured) + prep-v2: 16x32-point tiles, 325 blocks, 4 independent output
// chains/thread, both layouts from one SMEM tile. Prep was 7.0us at
// issue=26.6%; STG.128-issue floor is ~3.6us -> predict ~4.7us.

#define IH 384
#define IW 384
#define PAD 38
#define HP 460
#define WP 460
#define NA 64
#define NB 4

#define QR 385            // valid floor-coord index range [0,384]
#define PR 386            // stored point rows 0..385
#define PC 392            // point row stride: 392*16B = 49 x 128B lines
#define QBASE (PAD - 1)
#define NWB   115         // 4-i groups per angle
#define NWBG  29          // groups of 4 i-groups (16 i's per block)
#define NTR   25          // 16-point row tiles  (400 >= 386)
#define NTC   13          // 32-point col tiles  (416 >= 385)

// 2 layouts * 386 * 392 * 16B = 4.84 MB (.bss).
// g_p[l][r][c] = { h2(b0.L,b0.R), h2(b1.L,b1.R), h2(b2.L,b2.R), h2(b3.L,b3.R) }
// where L = px[r-1][c-1], R = px[r-1][c] (layout 0; transposed for l=1).
__device__ uint4 g_p[2][PR][PC];
// Column partials: [group][(b*32+a)*460 + j], 6.8 MB, fully rewritten.
__device__ float g_colpart[NWBG][NB * 32 * HP];

__device__ __forceinline__ unsigned packh2(float a, float b) {
    __half2 h = __floats2half2_rn(a, b);
    unsigned u;
    memcpy(&u, &h, 4);
    return u;
}

__device__ __forceinline__ __half2 h2cast(unsigned u) {
    __half2 h;
    memcpy(&h, &u, 4);
    return h;
}

// prep-v2: block = 16-row x 32-col point tile. SMEM = img rows [R0-1,R0+15]
// x cols [C0-1,C0+31] for all 4 batches. Emits 512 layout-0 points AND the
// corresponding 512 layout-1 points (RP in [C0,C0+31], CP in [R0,R0+15]).
__global__ __launch_bounds__(256) void prep_kernel(const float* __restrict__ x) {
    __shared__ float sh[NB][17][33];

    int bid = blockIdx.x;
    int tcb = bid % NTC;
    int trb = bid / NTC;
    int R0 = trb * 16, C0 = tcb * 32;
    int IR0 = R0 - 1,  IC0 = C0 - 1;

    for (int idx = threadIdx.x; idx < NB * 17 * 33; idx += 256) {
        int k  = idx / (17 * 33);
        int rc = idx - k * (17 * 33);
        int yy = rc / 33, xx = rc - yy * 33;
        int gy = IR0 + yy, gx = IC0 + xx;
        float v = 0.0f;
        if (((unsigned)gy < IH) & ((unsigned)gx < IW))
            v = __ldg(x + k * (IH * IW) + gy * IW + gx);
        sh[k][yy][xx] = v;
    }
    __syncthreads();

    // layout 0: point(rp,cp) = h2 of img[rp-1][cp-1..cp] per batch
    #pragma unroll
    for (int k = 0; k < 2; ++k) {
        int o  = threadIdx.x + k * 256;
        int rl = o >> 5, cl = o & 31;
        int rp = R0 + rl, cp = C0 + cl;
        if ((rp < PR) & (cp < QR)) {
            uint4 v;
            v.x = packh2(sh[0][rl][cl], sh[0][rl][cl + 1]);
            v.y = packh2(sh[1][rl][cl], sh[1][rl][cl + 1]);
            v.z = packh2(sh[2][rl][cl], sh[2][rl][cl + 1]);
            v.w = packh2(sh[3][rl][cl], sh[3][rl][cl + 1]);
            g_p[0][rp][cp] = v;
        }
    }
    // layout 1: point(RP,CP): L=img[CP-1][RP-1]=sh[b][cpl][rpl],
    //                         R=img[CP][RP-1] =sh[b][cpl+1][rpl]
    // RP = C0 + (o>>4) (rpl 0..31), CP = R0 + (o&15) (cpl 0..15).
    #pragma unroll
    for (int k = 0; k < 2; ++k) {
        int o   = threadIdx.x + k * 256;
        int rpl = o >> 4, cpl = o & 15;
        int RP = C0 + rpl, CP = R0 + cpl;
        if ((RP < PR) & (CP < QR)) {
            uint4 v;
            v.x = packh2(sh[0][cpl][rpl], sh[0][cpl + 1][rpl]);
            v.y = packh2(sh[1][cpl][rpl], sh[1][cpl + 1][rpl]);
            v.z = packh2(sh[2][cpl][rpl], sh[2][cpl + 1][rpl]);
            v.w = packh2(sh[3][cpl][rpl], sh[3][cpl + 1][rpl]);
            g_p[1][RP][CP] = v;
        }
    }
}

// Scalar fp32 lerp from a (top,bot) pair of h2(L,R) words (one batch).
__device__ __forceinline__ float lerp2(unsigned top, unsigned bot,
                                       float wC, float wR) {
    float2 t = __half22float2(h2cast(top));
    float2 b = __half22float2(h2cast(bot));
    float h0 = fmaf(wC, t.y - t.x, t.x);
    float h1 = fmaf(wC, b.y - b.x, b.x);
    return fmaf(wR, h1 - h0, h0);
}

// Block = (a<32, wgrp): 8 warps = 4 i-groups (wl) x 2 j-halves.
// Warp: i = (wgrp*4 + wl)*4 + isub, lane = isub*8 + jsub; j over its half.
// Each warp produces ALL 4 batches.
__global__ __launch_bounds__(256) void radon_kernel(float* __restrict__ out)
{
    __shared__ float colsh[NB][4][464];
    __shared__ float rowsh[NB][16][2];

    const int wgrp = blockIdx.x % NWBG;
    const int a    = blockIdx.x / NWBG;

    const int wid   = threadIdx.x >> 5;
    const int lane  = threadIdx.x & 31;
    const int wl    = wid & 3;
    const int jhalf = wid >> 2;
    const int wblk  = wgrp * 4 + wl;
    const bool valid = (wblk < NWB);

    const int isub = lane >> 3;
    const int jsub = lane & 7;
    const int i    = wblk * 4 + isub;
    const int il   = wl * 4 + isub;          // i_local in [0,16)

    float c, s;
    {
        float deg = 2.8125f * (float)a;
        float th  = deg * (float)(3.14159265358979323846 / 180.0);
        sincosf(th, &s, &c);
    }

    if (valid) {
        const float u  = (float)i - 229.5f;
        const float SH = 229.5f - (float)QBASE;

        const bool tmode = fabsf(c) > fabsf(s);
        const float Rv = tmode ? -s : c;
        const float Cv = tmode ?  c : -s;
        const float R0 = (tmode ? c * u : s * u) + SH;
        const float C0 = (tmode ? s * u : c * u) + SH;
        const uint4* __restrict__ base = &g_p[tmode ? 1 : 0][0][0];

        float acc0 = 0.f, acc1 = 0.f, acc2 = 0.f, acc3 = 0.f;
        const int j0 = jhalf * 232;
        float vf = (float)(j0 + jsub) - 229.5f;
        int   j  = j0 + jsub;

        // jhalf0: 29 full iters (j<232). jhalf1: 28 full + tail (j<460).
        #pragma unroll 4
        for (int it = 0; it < 28; ++it, vf += 8.0f, j += 8) {
            float R = fmaf(Rv, vf, R0);
            float C = fmaf(Cv, vf, C0);
            int   rq = __float2int_rd(R);
            int   cq = __float2int_rd(C);
            float wR = R - (float)rq;
            float wC = C - (float)cq;

            float v0 = 0.f, v1 = 0.f, v2 = 0.f, v3 = 0.f;
            if (((unsigned)rq < (unsigned)QR) & ((unsigned)cq < (unsigned)QR)) {
                const uint4* p = base + rq * PC + cq;
                uint4 P0 = __ldg(p);
                uint4 P1 = __ldg(p + PC);
                v0 = lerp2(P0.x, P1.x, wC, wR);
                v1 = lerp2(P0.y, P1.y, wC, wR);
                v2 = lerp2(P0.z, P1.z, wC, wR);
                v3 = lerp2(P0.w, P1.w, wC, wR);
            }
            acc0 += v0; acc1 += v1; acc2 += v2; acc3 += v3;
            v0 += __shfl_xor_sync(0xffffffffu, v0, 8);
            v0 += __shfl_xor_sync(0xffffffffu, v0, 16);
            v1 += __shfl_xor_sync(0xffffffffu, v1, 8);
            v1 += __shfl_xor_sync(0xffffffffu, v1, 16);
            v2 += __shfl_xor_sync(0xffffffffu, v2, 8);
            v2 += __shfl_xor_sync(0xffffffffu, v2, 16);
            v3 += __shfl_xor_sync(0xffffffffu, v3, 8);
            v3 += __shfl_xor_sync(0xffffffffu, v3, 16);
            if (isub == 0) {
                colsh[0][wl][j] = v0; colsh[1][wl][j] = v1;
                colsh[2][wl][j] = v2; colsh[3][wl][j] = v3;
            }
        }
        {   // iteration 29: jhalf0 full (j=224..231); jhalf1 only jsub<4 (456..459)
            bool ok = (jhalf == 0) | (jsub < 4);
            float v0 = 0.f, v1 = 0.f, v2 = 0.f, v3 = 0.f;
            if (ok) {
                float R = fmaf(Rv, vf, R0);
                float C = fmaf(Cv, vf, C0);
                int   rq = __float2int_rd(R);
                int   cq = __float2int_rd(C);
                float wR = R - (float)rq;
                float wC = C - (float)cq;
                if (((unsigned)rq < (unsigned)QR) & ((unsigned)cq < (unsigned)QR)) {
                    const uint4* p = base + rq * PC + cq;
                    uint4 P0 = __ldg(p);
                    uint4 P1 = __ldg(p + PC);
                    v0 = lerp2(P0.x, P1.x, wC, wR);
                    v1 = lerp2(P0.y, P1.y, wC, wR);
                    v2 = lerp2(P0.z, P1.z, wC, wR);
                    v3 = lerp2(P0.w, P1.w, wC, wR);
                }
            }
            acc0 += v0; acc1 += v1; acc2 += v2; acc3 += v3;
            v0 += __shfl_xor_sync(0xffffffffu, v0, 8);
            v0 += __shfl_xor_sync(0xffffffffu, v0, 16);
            v1 += __shfl_xor_sync(0xffffffffu, v1, 8);
            v1 += __shfl_xor_sync(0xffffffffu, v1, 16);
            v2 += __shfl_xor_sync(0xffffffffu, v2, 8);
            v2 += __shfl_xor_sync(0xffffffffu, v2, 16);
            v3 += __shfl_xor_sync(0xffffffffu, v3, 8);
            v3 += __shfl_xor_sync(0xffffffffu, v3, 16);
            if ((isub == 0) & ok) {
                colsh[0][wl][j] = v0; colsh[1][wl][j] = v1;
                colsh[2][wl][j] = v2; colsh[3][wl][j] = v3;
            }
        }

        // row partial: reduce each acc over the 8 jsub lanes
        #pragma unroll
        for (int off = 4; off; off >>= 1) {
            acc0 += __shfl_xor_sync(0xffffffffu, acc0, off);
            acc1 += __shfl_xor_sync(0xffffffffu, acc1, off);
            acc2 += __shfl_xor_sync(0xffffffffu, acc2, off);
            acc3 += __shfl_xor_sync(0xffffffffu, acc3, off);
        }
        if (jsub == 0) {
            rowsh[0][il][jhalf] = acc0;
            rowsh[1][il][jhalf] = acc1;
            rowsh[2][il][jhalf] = acc2;
            rowsh[3][il][jhalf] = acc3;
        }
    } else {
        // invalid warp (only wgrp=28, wl=3): zero its colsh range + rowsh rows
        const int j0 = jhalf * 232, j1 = jhalf ? 460 : 232;
        for (int j = j0 + lane; j < j1; j += 32) {
            colsh[0][wl][j] = 0.f; colsh[1][wl][j] = 0.f;
            colsh[2][wl][j] = 0.f; colsh[3][wl][j] = 0.f;
        }
        if (jsub == 0) {
            rowsh[0][il][jhalf] = 0.f; rowsh[1][il][jhalf] = 0.f;
            rowsh[2][il][jhalf] = 0.f; rowsh[3][il][jhalf] = 0.f;
        }
    }

    __syncthreads();

    // row outputs: 4 batches x 16 i_locals -> angle a+32
    if (threadIdx.x < NB * 16) {
        int b  = threadIdx.x >> 4;
        int il2 = threadIdx.x & 15;
        int ii = wgrp * 16 + il2;
        if (ii < 460) {
            float v = rowsh[b][il2][0] + rowsh[b][il2][1];
            out[(b * HP + (459 - ii)) * NA + (a + 32)] = v * (1.0f / (float)WP);
        }
    }

    // column partials: reduce 4 wl slices per (b, j)
    for (int t = threadIdx.x; t < NB * HP; t += 256) {
        int b = t / HP, j = t - b * HP;
        float sum = colsh[b][0][j] + colsh[b][1][j]
                  + colsh[b][2][j] + colsh[b][3][j];
        g_colpart[wgrp][(b * 32 + a) * HP + j] = sum;
    }
}

// Sum the 29 group partials per (b, a<32, j) -> angle a output.
__global__ __launch_bounds__(256) void combine_kernel(float* __restrict__ out)
{
    int t = blockIdx.x * blockDim.x + threadIdx.x;
    if (t >= NB * 32 * HP) return;
    float sum = 0.0f;
    #pragma unroll
    for (int g = 0; g < NWBG; ++g)
        sum += g_colpart[g][t];
    int j  = t % HP;
    int ba = t / HP;
    int a  = ba & 31;
    int b  = ba >> 5;
    out[(b * HP + j) * NA + a] = sum * (1.0f / (float)WP);
}

extern "C" void kernel_launch(void* const* d_in, const int* in_sizes, int n_in,
                              void* d_out, int out_size) {
    (void)in_sizes; (void)n_in; (void)out_size;
    const float* x = (const float*)d_in[0];
    float* out = (float*)d_out;

    prep_kernel<<<NTR * NTC, 256>>>(x);            // 325 blocks

    radon_kernel<<<32 * NWBG, 256>>>(out);         // 928 blocks

    const int ncomb = NB * 32 * HP;                 // 58880
    combine_kernel<<<(ncomb + 255) / 256, 256>>>(out);
}